// round 1
// baseline (speedup 1.0000x reference)
#include <cuda_runtime.h>
#include <cuda_bf16.h>
#include <cstdint>

// Problem constants
#define BB 16
#define SS 2048
#define HH 512
#define AA 256
#define BS (BB*SS)            // 32768 tokens
#define A_ELEMS ((size_t)BS*HH)  // offset of d in output

// Scratch (device globals — no allocation allowed)
__device__ float g_e[BS];
__device__ float g_w[BS];
__device__ float g_ip[BS];
#define NC 16
#define CS 128
__device__ float g_chunk[BB*NC*HH];

// ---------------------------------------------------------------------------
// Kernel 1: e[b,t] = sum_a q[a] * tanh( sum_h W[a,h] * x[b,t,h] )
// SGEMM M=32768 (tokens) x N=256 (A, full) x K=512, with packed f32x2 FMA.
// CTA: 64 tokens, 256 threads (8 warps). warp -> 8 tokens, lane -> 4 a-pairs
// (a = j*64 + 2*lane + {0,1}).
// ---------------------------------------------------------------------------
__global__ __launch_bounds__(256, 2) void e_kernel(
    const float* __restrict__ x, const float* __restrict__ W,
    const float* __restrict__ q)
{
    __shared__ __align__(16) float xs[16*65];    // xs[k*65 + m]
    __shared__ __align__(16) float ws[16*258];   // ws[k*258 + a] (even stride for LDS.64)

    const int tid  = threadIdx.x;
    const int warp = tid >> 5;
    const int lane = tid & 31;
    const size_t m0 = (size_t)blockIdx.x * 64;

    unsigned long long acc[8][4];
#pragma unroll
    for (int i = 0; i < 8; i++)
#pragma unroll
        for (int j = 0; j < 4; j++) acc[i][j] = 0ull;

    for (int kk = 0; kk < HH; kk += 16) {
        // x tile: 64 tokens x 16 k  (coalesced float4)
        {
            const int m_l = tid >> 2;
            const int kq  = (tid & 3) * 4;
            const float4 xv = *(const float4*)(x + (m0 + m_l)*HH + kk + kq);
            xs[(kq+0)*65 + m_l] = xv.x;
            xs[(kq+1)*65 + m_l] = xv.y;
            xs[(kq+2)*65 + m_l] = xv.z;
            xs[(kq+3)*65 + m_l] = xv.w;
        }
        // W tile: 256 a x 16 k (coalesced float4, transposed into smem)
#pragma unroll
        for (int i = 0; i < 4; i++) {
            const int F  = i*256 + tid;       // float4 index
            const int a  = F >> 2;
            const int c4 = F & 3;
            const float4 wv = *(const float4*)(W + a*HH + kk + c4*4);
            ws[(c4*4+0)*258 + a] = wv.x;
            ws[(c4*4+1)*258 + a] = wv.y;
            ws[(c4*4+2)*258 + a] = wv.z;
            ws[(c4*4+3)*258 + a] = wv.w;
        }
        __syncthreads();

#pragma unroll
        for (int k = 0; k < 16; k++) {
            unsigned long long xp[8];
#pragma unroll
            for (int i = 0; i < 8; i++) {
                const unsigned int xu = __float_as_uint(xs[k*65 + warp*8 + i]);
                asm("mov.b64 %0, {%1, %1};" : "=l"(xp[i]) : "r"(xu));
            }
            unsigned long long wp[4];
#pragma unroll
            for (int j = 0; j < 4; j++)
                wp[j] = *(const unsigned long long*)(&ws[k*258 + j*64 + lane*2]);
#pragma unroll
            for (int i = 0; i < 8; i++)
#pragma unroll
                for (int j = 0; j < 4; j++)
                    asm("fma.rn.f32x2 %0, %1, %2, %0;"
                        : "+l"(acc[i][j]) : "l"(xp[i]), "l"(wp[j]));
        }
        __syncthreads();
    }

    // Epilogue: e_partial = sum_j q[a]*tanh(acc), warp-reduce over lanes.
    const float2* q2 = (const float2*)q;
    float sums[8];
#pragma unroll
    for (int i = 0; i < 8; i++) {
        float s = 0.f;
#pragma unroll
        for (int j = 0; j < 4; j++) {
            const float2 qv = q2[j*32 + lane];
            unsigned int lo, hi;
            asm("mov.b64 {%0, %1}, %2;" : "=r"(lo), "=r"(hi) : "l"(acc[i][j]));
            s += qv.x * tanhf(__uint_as_float(lo));
            s += qv.y * tanhf(__uint_as_float(hi));
        }
        sums[i] = s;
    }
#pragma unroll
    for (int off = 16; off; off >>= 1)
#pragma unroll
        for (int i = 0; i < 8; i++)
            sums[i] += __shfl_down_sync(0xffffffffu, sums[i], off);
    if (lane == 0) {
#pragma unroll
        for (int i = 0; i < 8; i++)
            g_e[m0 + warp*8 + i] = sums[i];
    }
}

// ---------------------------------------------------------------------------
// Kernel 2: per-batch  w_t = exp(e_t - max), inclusive prefix P_s, ip = 1/P_s
// One block per batch, 256 threads, 8 contiguous elems per thread.
// ---------------------------------------------------------------------------
__global__ __launch_bounds__(256) void scan_kernel()
{
    __shared__ float se[SS];
    __shared__ float sr[256];
    const int b   = blockIdx.x;
    const int tid = threadIdx.x;
    const int base = b * SS;

    for (int i = tid; i < SS; i += 256) se[i] = g_e[base + i];
    __syncthreads();

    float m = -1e30f;
    for (int i = tid; i < SS; i += 256) m = fmaxf(m, se[i]);
    sr[tid] = m;
    __syncthreads();
    for (int o = 128; o; o >>= 1) {
        if (tid < o) sr[tid] = fmaxf(sr[tid], sr[tid + o]);
        __syncthreads();
    }
    const float M = sr[0];
    __syncthreads();

    const int j0 = tid * 8;
    float wloc[8];
    float run = 0.f;
#pragma unroll
    for (int j = 0; j < 8; j++) {
        wloc[j] = expf(se[j0 + j] - M);
        run += wloc[j];
    }
    sr[tid] = run;
    __syncthreads();
    // Hillis-Steele inclusive scan over 256 thread-totals
    for (int o = 1; o < 256; o <<= 1) {
        const float v = (tid >= o) ? sr[tid - o] : 0.f;
        __syncthreads();
        sr[tid] += v;
        __syncthreads();
    }
    float acc = sr[tid] - run;   // exclusive offset
#pragma unroll
    for (int j = 0; j < 8; j++) {
        acc += wloc[j];
        g_w [base + j0 + j] = wloc[j];
        g_ip[base + j0 + j] = 1.0f / acc;
    }
}

// ---------------------------------------------------------------------------
// Kernel 3a: chunk-local sums T[b,c,h] = sum_{t in chunk} w_t * x[b,t,h]
// grid (H/128, NC, B), 128 threads, thread = one h column.
// ---------------------------------------------------------------------------
__global__ __launch_bounds__(128) void chunk_kernel(const float* __restrict__ x)
{
    __shared__ float sw[CS];
    const int h = blockIdx.x * 128 + threadIdx.x;
    const int c = blockIdx.y;
    const int b = blockIdx.z;
    const int tbase = b * SS + c * CS;
    sw[threadIdx.x] = g_w[tbase + threadIdx.x];
    __syncthreads();

    const float* xp = x + (size_t)tbase * HH + h;
    float s = 0.f;
#pragma unroll 4
    for (int t = 0; t < CS; t++) s = fmaf(sw[t], xp[(size_t)t * HH], s);
    g_chunk[(b * NC + c) * HH + h] = s;
}

// ---------------------------------------------------------------------------
// Kernel 3b: a[b,s,h] = (chunk-prefix + running sum) * ip[b,s]
// ---------------------------------------------------------------------------
__global__ __launch_bounds__(128) void a_kernel(
    const float* __restrict__ x, float* __restrict__ a_out)
{
    __shared__ float sw[CS];
    __shared__ float sip[CS];
    const int h = blockIdx.x * 128 + threadIdx.x;
    const int c = blockIdx.y;
    const int b = blockIdx.z;
    const int tbase = b * SS + c * CS;
    sw [threadIdx.x] = g_w [tbase + threadIdx.x];
    sip[threadIdx.x] = g_ip[tbase + threadIdx.x];
    __syncthreads();

    float acc = 0.f;
    for (int cp = 0; cp < c; cp++) acc += g_chunk[(b * NC + cp) * HH + h];

    const float* xp = x     + (size_t)tbase * HH + h;
    float*       op = a_out + (size_t)tbase * HH + h;
#pragma unroll 4
    for (int t = 0; t < CS; t++) {
        acc = fmaf(sw[t], xp[(size_t)t * HH], acc);
        op[(size_t)t * HH] = acc * sip[t];
    }
}

// ---------------------------------------------------------------------------
// Kernel 4: d[b,s,t] = (t<=s) ? w[b,t]*ip[b,s] : 0   — pure streaming store.
// One block per (b,s) row, 128 threads, float4 writes.
// ---------------------------------------------------------------------------
__global__ __launch_bounds__(128) void d_kernel(float* __restrict__ dd)
{
    const int row = blockIdx.x;          // b*S + s
    const int b = row >> 11;
    const int s = row & (SS - 1);
    const float ip = g_ip[row];
    const float4* w4 = (const float4*)(g_w + ((size_t)b << 11));
    float4* o4 = (float4*)(dd + (size_t)row * SS);

    for (int i = threadIdx.x; i < SS / 4; i += 128) {
        const int t0 = i * 4;
        float4 r;
        if (t0 + 3 <= s) {
            const float4 wv = w4[i];
            r.x = wv.x * ip; r.y = wv.y * ip; r.z = wv.z * ip; r.w = wv.w * ip;
        } else if (t0 > s) {
            r.x = r.y = r.z = r.w = 0.f;
        } else {
            const float4 wv = w4[i];
            r.x = (t0     <= s) ? wv.x * ip : 0.f;
            r.y = (t0 + 1 <= s) ? wv.y * ip : 0.f;
            r.z = (t0 + 2 <= s) ? wv.z * ip : 0.f;
            r.w = (t0 + 3 <= s) ? wv.w * ip : 0.f;
        }
        o4[i] = r;
    }
}

// ---------------------------------------------------------------------------
extern "C" void kernel_launch(void* const* d_in, const int* in_sizes, int n_in,
                              void* d_out, int out_size)
{
    const float* x = (const float*)d_in[0];   // [B,S,H]
    const float* W = (const float*)d_in[1];   // [A,H]
    const float* q = (const float*)d_in[2];   // [1,A]
    float* a_out = (float*)d_out;             // [B,S,1,H]
    float* dd    = (float*)d_out + A_ELEMS;   // [B,S,1,S]

    e_kernel    <<<BS / 64, 256>>>(x, W, q);
    scan_kernel <<<BB, 256>>>();
    chunk_kernel<<<dim3(HH / 128, NC, BB), 128>>>(x);
    a_kernel    <<<dim3(HH / 128, NC, BB), 128>>>(x, a_out);
    d_kernel    <<<BS, 128>>>(dd);
}

// round 3
// speedup vs baseline: 1.4796x; 1.4796x over previous
#include <cuda_runtime.h>
#include <cuda_bf16.h>
#include <cstdint>

// Problem constants
#define BB 16
#define SS 2048
#define HH 512
#define AA 256
#define BS (BB*SS)               // 32768 tokens
#define A_ELEMS ((size_t)BS*HH)  // offset of d in output

// Scratch (device globals — no allocation allowed)
__device__ float g_ep[2*BS];     // per-n-half partial e
__device__ float g_w[BS];
__device__ float g_ip[BS];
#define NC 16
#define CS 128
__device__ float g_chunk[BB*NC*HH];
// W split into bf16 hi/lo, packed as bf16x2 (uint32), [256 rows][256 pairs]
__device__ unsigned int g_whi[AA*HH/2];
__device__ unsigned int g_wlo[AA*HH/2];

// ---------------------------------------------------------------------------
__device__ __forceinline__ uint32_t smem_u32(const void* p) {
    uint32_t a;
    asm("{ .reg .u64 t; cvta.to.shared.u64 t, %1; cvt.u32.u64 %0, t; }"
        : "=r"(a) : "l"(p));
    return a;
}

#define LDSM_X4(r, addr) \
    asm volatile("ldmatrix.sync.aligned.m8n8.x4.shared.b16 {%0,%1,%2,%3}, [%4];" \
        : "=r"((r)[0]), "=r"((r)[1]), "=r"((r)[2]), "=r"((r)[3]) : "r"(addr))

#define HMMA16816(d, a, b0, b1) \
    asm volatile("mma.sync.aligned.m16n8k16.row.col.f32.bf16.bf16.f32 " \
        "{%0,%1,%2,%3},{%4,%5,%6,%7},{%8,%9},{%0,%1,%2,%3};" \
        : "+f"((d)[0]), "+f"((d)[1]), "+f"((d)[2]), "+f"((d)[3]) \
        : "r"((a)[0]), "r"((a)[1]), "r"((a)[2]), "r"((a)[3]), "r"(b0), "r"(b1))

__device__ __forceinline__ float fast_tanh(float v) {
    float t; asm("ex2.approx.f32 %0, %1;" : "=f"(t) : "f"(v * 2.885390081777927f));
    float r; asm("rcp.approx.f32 %0, %1;" : "=f"(r) : "f"(t + 1.0f));
    return fmaf(-2.0f, r, 1.0f);   // tanh(v) = 1 - 2/(e^{2v}+1)
}

// ---------------------------------------------------------------------------
// Kernel 0: split W [256,512] fp32 into bf16 hi/lo packed pairs
// ---------------------------------------------------------------------------
__global__ __launch_bounds__(256) void wsplit_kernel(const float* __restrict__ W)
{
    const int i = blockIdx.x * 256 + threadIdx.x;   // pair index
    const float2 v = ((const float2*)W)[i];
    __nv_bfloat162 hp = __floats2bfloat162_rn(v.x, v.y);
    unsigned int hu = *(unsigned int*)&hp;
    float hf0 = __uint_as_float(hu << 16);
    float hf1 = __uint_as_float(hu & 0xffff0000u);
    __nv_bfloat162 lp = __floats2bfloat162_rn(v.x - hf0, v.y - hf1);
    g_whi[i] = hu;
    g_wlo[i] = *(unsigned int*)&lp;
}

// ---------------------------------------------------------------------------
// Kernel 1: e-partial via mma.sync bf16 (3-term split).
// CTA tile: M=128 tokens x N=128 A-cols (blockIdx.y selects half), K chunks 64.
// 8 warps in 4(m) x 2(n): warp tile 32x64, accum 2x8 HMMA frags.
// smem rows padded to 144B (72 bf16) for conflict-free ldmatrix.
// ---------------------------------------------------------------------------
#define RSTRIDE 144              // bytes per smem row (64 bf16 + 8 pad)
#define SM_XHI  0
#define SM_XLO  18432
#define SM_WHI  36864
#define SM_WLO  55296
#define SM_Q    73728
#define SM_TOTAL 74752

__global__ __launch_bounds__(256, 2) void e_mma_kernel(
    const float* __restrict__ x, const float* __restrict__ q)
{
    extern __shared__ __align__(128) char smem[];
    const uint32_t sb = smem_u32(smem);
    const int tid  = threadIdx.x;
    const int lane = tid & 31;
    const int warp = tid >> 5;
    const int warp_m = warp & 3;
    const int warp_n = warp >> 2;
    const size_t m0 = (size_t)blockIdx.x * 128;
    const int n0 = blockIdx.y * 128;

    float* sq = (float*)(smem + SM_Q);
    if (tid < 128) sq[tid] = q[n0 + tid];

    float acc[2][8][4];
#pragma unroll
    for (int mt = 0; mt < 2; mt++)
#pragma unroll
        for (int nt = 0; nt < 8; nt++)
#pragma unroll
            for (int j = 0; j < 4; j++) acc[mt][nt][j] = 0.f;

    // per-lane ldmatrix address offsets (bytes)
    const uint32_t a_off = (lane & 15) * RSTRIDE + ((lane >> 4) << 4);
    const uint32_t b_off = ((((lane >> 4) & 1) << 3) + (lane & 7)) * RSTRIDE
                         + (((lane >> 3) & 1) << 4);
    const uint32_t axhi = sb + SM_XHI + warp_m * 32 * RSTRIDE + a_off;
    const uint32_t axlo = axhi + (SM_XLO - SM_XHI);
    const uint32_t bwhi = sb + SM_WHI + warp_n * 64 * RSTRIDE + b_off;
    const uint32_t bwlo = bwhi + (SM_WLO - SM_WHI);

    const uint4* wh4 = (const uint4*)g_whi;   // [a][64 uint4 per row]
    const uint4* wl4 = (const uint4*)g_wlo;

    for (int c = 0; c < 8; c++) {
        const int kk = c * 64;

        // Prefetch X fp32 tile (128 x 64) into regs (overlaps prev compute)
        float4 xv[8];
#pragma unroll
        for (int i = 0; i < 8; i++) {
            const int idx = i * 256 + tid;
            const int row = idx >> 4;
            const int f4  = idx & 15;
            xv[i] = *(const float4*)(x + (m0 + row) * HH + kk + f4 * 4);
        }

        __syncthreads();   // prev chunk's ldmatrix reads complete

        // X -> bf16 hi/lo into smem
#pragma unroll
        for (int i = 0; i < 8; i++) {
            const int idx = i * 256 + tid;
            const int row = idx >> 4;
            const int f4  = idx & 15;
            const uint32_t bo = row * RSTRIDE + f4 * 8;
            float v0 = xv[i].x, v1 = xv[i].y, v2 = xv[i].z, v3 = xv[i].w;
            __nv_bfloat162 h01 = __floats2bfloat162_rn(v0, v1);
            __nv_bfloat162 h23 = __floats2bfloat162_rn(v2, v3);
            const unsigned int hu01 = *(unsigned int*)&h01;
            const unsigned int hu23 = *(unsigned int*)&h23;
            float l0 = v0 - __uint_as_float(hu01 << 16);
            float l1 = v1 - __uint_as_float(hu01 & 0xffff0000u);
            float l2 = v2 - __uint_as_float(hu23 << 16);
            float l3 = v3 - __uint_as_float(hu23 & 0xffff0000u);
            __nv_bfloat162 lo01 = __floats2bfloat162_rn(l0, l1);
            __nv_bfloat162 lo23 = __floats2bfloat162_rn(l2, l3);
            unsigned long long hp, lp;
            asm("mov.b64 %0, {%1, %2};" : "=l"(hp) : "r"(hu01), "r"(hu23));
            asm("mov.b64 %0, {%1, %2};" : "=l"(lp)
                : "r"(*(unsigned int*)&lo01), "r"(*(unsigned int*)&lo23));
            *(unsigned long long*)(smem + SM_XHI + bo) = hp;
            *(unsigned long long*)(smem + SM_XLO + bo) = lp;
        }

        // W tiles (128 n-rows x 64 k) hi/lo — L2-hot
#pragma unroll
        for (int i = 0; i < 4; i++) {
            const int g  = i * 256 + tid;      // uint4 index, 1024 total
            const int row = g >> 3;
            const int cc  = g & 7;
            const uint32_t bo = row * RSTRIDE + cc * 16;
            const size_t gi = (size_t)(n0 + row) * 64 + (kk >> 3) + cc;
            *(uint4*)(smem + SM_WHI + bo) = wh4[gi];
            *(uint4*)(smem + SM_WLO + bo) = wl4[gi];
        }

        __syncthreads();

        // 3 terms x 4 k-steps of HMMA
#pragma unroll
        for (int term = 0; term < 3; term++) {
            const uint32_t ab = (term == 1) ? axlo : axhi;
            const uint32_t bb = (term == 2) ? bwlo : bwhi;
#pragma unroll
            for (int ks = 0; ks < 4; ks++) {
                uint32_t A0[4], A1[4], Bv[16];
                LDSM_X4(A0, ab + ks * 32);
                LDSM_X4(A1, ab + 16 * RSTRIDE + ks * 32);
#pragma unroll
                for (int jp = 0; jp < 4; jp++)
                    LDSM_X4(&Bv[jp * 4], bb + jp * 16 * RSTRIDE + ks * 32);
#pragma unroll
                for (int nt = 0; nt < 8; nt++) {
                    const int bi = (nt >> 1) * 4 + (nt & 1) * 2;
                    HMMA16816(acc[0][nt], A0, Bv[bi], Bv[bi + 1]);
                }
#pragma unroll
                for (int nt = 0; nt < 8; nt++) {
                    const int bi = (nt >> 1) * 4 + (nt & 1) * 2;
                    HMMA16816(acc[1][nt], A1, Bv[bi], Bv[bi + 1]);
                }
            }
        }
    }

    // Epilogue: s = sum_cols q[col]*tanh(D) per owned row
    float s[2][2] = {{0.f, 0.f}, {0.f, 0.f}};
#pragma unroll
    for (int mt = 0; mt < 2; mt++)
#pragma unroll
        for (int nt = 0; nt < 8; nt++) {
            const int col = warp_n * 64 + nt * 8 + 2 * (lane & 3);
            const float q0 = sq[col], q1 = sq[col + 1];
            s[mt][0] = fmaf(q0, fast_tanh(acc[mt][nt][0]),
                       fmaf(q1, fast_tanh(acc[mt][nt][1]), s[mt][0]));
            s[mt][1] = fmaf(q0, fast_tanh(acc[mt][nt][2]),
                       fmaf(q1, fast_tanh(acc[mt][nt][3]), s[mt][1]));
        }
#pragma unroll
    for (int mt = 0; mt < 2; mt++)
#pragma unroll
        for (int rh = 0; rh < 2; rh++) {
            float v = s[mt][rh];
            v += __shfl_xor_sync(0xffffffffu, v, 1);
            v += __shfl_xor_sync(0xffffffffu, v, 2);
            s[mt][rh] = v;
        }

    __syncthreads();               // all ldmatrix done; reuse smem
    float* red = (float*)smem;     // [2 warp_n][128 rows]
    if ((lane & 3) == 0) {
#pragma unroll
        for (int mt = 0; mt < 2; mt++)
#pragma unroll
            for (int rh = 0; rh < 2; rh++)
                red[warp_n * 128 + warp_m * 32 + mt * 16 + rh * 8 + (lane >> 2)]
                    = s[mt][rh];
    }
    __syncthreads();
    if (tid < 128)
        g_ep[(size_t)blockIdx.y * BS + m0 + tid] = red[tid] + red[128 + tid];
}

// ---------------------------------------------------------------------------
// Kernel 2: per-batch  w_t = exp(e_t - max), inclusive prefix P_s, ip = 1/P_s
// ---------------------------------------------------------------------------
__global__ __launch_bounds__(256) void scan_kernel()
{
    __shared__ float se[SS];
    __shared__ float sr[256];
    const int b   = blockIdx.x;
    const int tid = threadIdx.x;
    const int base = b * SS;

    for (int i = tid; i < SS; i += 256)
        se[i] = g_ep[base + i] + g_ep[BS + base + i];
    __syncthreads();

    float m = -1e30f;
    for (int i = tid; i < SS; i += 256) m = fmaxf(m, se[i]);
    sr[tid] = m;
    __syncthreads();
    for (int o = 128; o; o >>= 1) {
        if (tid < o) sr[tid] = fmaxf(sr[tid], sr[tid + o]);
        __syncthreads();
    }
    const float M = sr[0];
    __syncthreads();

    const int j0 = tid * 8;
    float wloc[8];
    float run = 0.f;
#pragma unroll
    for (int j = 0; j < 8; j++) {
        wloc[j] = expf(se[j0 + j] - M);
        run += wloc[j];
    }
    sr[tid] = run;
    __syncthreads();
    for (int o = 1; o < 256; o <<= 1) {
        const float v = (tid >= o) ? sr[tid - o] : 0.f;
        __syncthreads();
        sr[tid] += v;
        __syncthreads();
    }
    float acc = sr[tid] - run;
#pragma unroll
    for (int j = 0; j < 8; j++) {
        acc += wloc[j];
        g_w [base + j0 + j] = wloc[j];
        g_ip[base + j0 + j] = 1.0f / acc;
    }
}

// ---------------------------------------------------------------------------
// Kernel 3a: chunk-local sums T[b,c,h] = sum_{t in chunk} w_t * x[b,t,h]
// ---------------------------------------------------------------------------
__global__ __launch_bounds__(128) void chunk_kernel(const float* __restrict__ x)
{
    __shared__ float sw[CS];
    const int h = blockIdx.x * 128 + threadIdx.x;
    const int c = blockIdx.y;
    const int b = blockIdx.z;
    const int tbase = b * SS + c * CS;
    sw[threadIdx.x] = g_w[tbase + threadIdx.x];
    __syncthreads();

    const float* xp = x + (size_t)tbase * HH + h;
    float s = 0.f;
#pragma unroll 4
    for (int t = 0; t < CS; t++) s = fmaf(sw[t], xp[(size_t)t * HH], s);
    g_chunk[(b * NC + c) * HH + h] = s;
}

// ---------------------------------------------------------------------------
// Kernel 3b: a[b,s,h] = (chunk-prefix + running sum) * ip[b,s]
// ---------------------------------------------------------------------------
__global__ __launch_bounds__(128) void a_kernel(
    const float* __restrict__ x, float* __restrict__ a_out)
{
    __shared__ float sw[CS];
    __shared__ float sip[CS];
    const int h = blockIdx.x * 128 + threadIdx.x;
    const int c = blockIdx.y;
    const int b = blockIdx.z;
    const int tbase = b * SS + c * CS;
    sw [threadIdx.x] = g_w [tbase + threadIdx.x];
    sip[threadIdx.x] = g_ip[tbase + threadIdx.x];
    __syncthreads();

    float acc = 0.f;
    for (int cp = 0; cp < c; cp++) acc += g_chunk[(b * NC + cp) * HH + h];

    const float* xp = x     + (size_t)tbase * HH + h;
    float*       op = a_out + (size_t)tbase * HH + h;
#pragma unroll 4
    for (int t = 0; t < CS; t++) {
        acc = fmaf(sw[t], xp[(size_t)t * HH], acc);
        op[(size_t)t * HH] = acc * sip[t];
    }
}

// ---------------------------------------------------------------------------
// Kernel 4: d[b,s,t] = (t<=s) ? w[b,t]*ip[b,s] : 0
// ---------------------------------------------------------------------------
__global__ __launch_bounds__(128) void d_kernel(float* __restrict__ dd)
{
    const int row = blockIdx.x;
    const int b = row >> 11;
    const int s = row & (SS - 1);
    const float ip = g_ip[row];
    const float4* w4 = (const float4*)(g_w + ((size_t)b << 11));
    float4* o4 = (float4*)(dd + (size_t)row * SS);

    for (int i = threadIdx.x; i < SS / 4; i += 128) {
        const int t0 = i * 4;
        float4 r;
        if (t0 + 3 <= s) {
            const float4 wv = w4[i];
            r.x = wv.x * ip; r.y = wv.y * ip; r.z = wv.z * ip; r.w = wv.w * ip;
        } else if (t0 > s) {
            r.x = r.y = r.z = r.w = 0.f;
        } else {
            const float4 wv = w4[i];
            r.x = (t0     <= s) ? wv.x * ip : 0.f;
            r.y = (t0 + 1 <= s) ? wv.y * ip : 0.f;
            r.z = (t0 + 2 <= s) ? wv.z * ip : 0.f;
            r.w = (t0 + 3 <= s) ? wv.w * ip : 0.f;
        }
        o4[i] = r;
    }
}

// ---------------------------------------------------------------------------
extern "C" void kernel_launch(void* const* d_in, const int* in_sizes, int n_in,
                              void* d_out, int out_size)
{
    const float* x = (const float*)d_in[0];   // [B,S,H]
    const float* W = (const float*)d_in[1];   // [A,H]
    const float* q = (const float*)d_in[2];   // [1,A]
    float* a_out = (float*)d_out;             // [B,S,1,H]
    float* dd    = (float*)d_out + A_ELEMS;   // [B,S,1,S]

    cudaFuncSetAttribute(e_mma_kernel,
                         cudaFuncAttributeMaxDynamicSharedMemorySize, SM_TOTAL);

    wsplit_kernel<<<AA * HH / 512, 256>>>(W);
    e_mma_kernel <<<dim3(BS / 128, 2), 256, SM_TOTAL>>>(x, q);
    scan_kernel  <<<BB, 256>>>();
    chunk_kernel <<<dim3(HH / 128, NC, BB), 128>>>(x);
    a_kernel     <<<dim3(HH / 128, NC, BB), 128>>>(x, a_out);
    d_kernel     <<<BS, 128>>>(dd);
}

// round 4
// speedup vs baseline: 1.7190x; 1.1619x over previous
#include <cuda_runtime.h>
#include <cuda_fp16.h>
#include <cstdint>

// Problem constants
#define BB 16
#define SS 2048
#define HH 512
#define AA 256
#define BS (BB*SS)               // 32768 tokens
#define A_ELEMS ((size_t)BS*HH)  // offset of d in output

// Scratch (device globals — no allocation allowed)
__device__ float g_ep[2*BS];     // per-n-half partial e
__device__ float g_w[BS];
__device__ float g_ip[BS];
#define NC 16
#define CS 128
__device__ float g_chunk[BB*NC*HH];
// W as fp16 pairs (uint32 = half2), [256 rows][256 pairs]
__device__ unsigned int g_wh[AA*HH/2];

// ---------------------------------------------------------------------------
__device__ __forceinline__ uint32_t smem_u32(const void* p) {
    uint32_t a;
    asm("{ .reg .u64 t; cvta.to.shared.u64 t, %1; cvt.u32.u64 %0, t; }"
        : "=r"(a) : "l"(p));
    return a;
}

#define LDSM_X4(r, addr) \
    asm volatile("ldmatrix.sync.aligned.m8n8.x4.shared.b16 {%0,%1,%2,%3}, [%4];" \
        : "=r"((r)[0]), "=r"((r)[1]), "=r"((r)[2]), "=r"((r)[3]) : "r"(addr))

#define HMMA16816(d, a, b0, b1) \
    asm volatile("mma.sync.aligned.m16n8k16.row.col.f32.f16.f16.f32 " \
        "{%0,%1,%2,%3},{%4,%5,%6,%7},{%8,%9},{%0,%1,%2,%3};" \
        : "+f"((d)[0]), "+f"((d)[1]), "+f"((d)[2]), "+f"((d)[3]) \
        : "r"((a)[0]), "r"((a)[1]), "r"((a)[2]), "r"((a)[3]), "r"(b0), "r"(b1))

__device__ __forceinline__ float fast_tanh(float v) {
    float t; asm("ex2.approx.f32 %0, %1;" : "=f"(t) : "f"(v * 2.885390081777927f));
    float r; asm("rcp.approx.f32 %0, %1;" : "=f"(r) : "f"(t + 1.0f));
    return fmaf(-2.0f, r, 1.0f);   // tanh(v) = 1 - 2/(e^{2v}+1)
}

// ---------------------------------------------------------------------------
// Kernel 0: W [256,512] fp32 -> fp16 pairs
// ---------------------------------------------------------------------------
__global__ __launch_bounds__(256) void wsplit_kernel(const float* __restrict__ W)
{
    const int i = blockIdx.x * 256 + threadIdx.x;   // pair index
    const float2 v = ((const float2*)W)[i];
    __half2 hp = __floats2half2_rn(v.x, v.y);
    g_wh[i] = *(unsigned int*)&hp;
}

// ---------------------------------------------------------------------------
// Kernel 1: e-partial via mma.sync fp16, 2-term X split (xh + xl), W fp16.
// CTA tile: M=128 tokens x N=128 A-cols (blockIdx.y), K chunks of 64.
// 8 warps 4(m) x 2(n); warp tile 32x64.
// ---------------------------------------------------------------------------
#define RSTRIDE 144              // bytes per smem row (64 fp16 + pad)
#define SM_XHI  0
#define SM_XLO  18432
#define SM_WHI  36864
#define SM_Q    55296
#define SM_TOTAL 55808

__global__ __launch_bounds__(256, 2) void e_mma_kernel(
    const float* __restrict__ x, const float* __restrict__ q)
{
    extern __shared__ __align__(128) char smem[];
    const uint32_t sb = smem_u32(smem);
    const int tid  = threadIdx.x;
    const int lane = tid & 31;
    const int warp = tid >> 5;
    const int warp_m = warp & 3;
    const int warp_n = warp >> 2;
    const size_t m0 = (size_t)blockIdx.x * 128;
    const int n0 = blockIdx.y * 128;

    float* sq = (float*)(smem + SM_Q);
    if (tid < 128) sq[tid] = q[n0 + tid];

    float acc[2][8][4];
#pragma unroll
    for (int mt = 0; mt < 2; mt++)
#pragma unroll
        for (int nt = 0; nt < 8; nt++)
#pragma unroll
            for (int j = 0; j < 4; j++) acc[mt][nt][j] = 0.f;

    // per-lane ldmatrix address offsets (bytes)
    const uint32_t a_off = (lane & 15) * RSTRIDE + ((lane >> 4) << 4);
    const uint32_t b_off = ((((lane >> 4) & 1) << 3) + (lane & 7)) * RSTRIDE
                         + (((lane >> 3) & 1) << 4);
    const uint32_t axhi = sb + SM_XHI + warp_m * 32 * RSTRIDE + a_off;
    const uint32_t axlo = axhi + (SM_XLO - SM_XHI);
    const uint32_t bwhi = sb + SM_WHI + warp_n * 64 * RSTRIDE + b_off;

    const uint4* wh4 = (const uint4*)g_wh;   // [a][64 uint4 per row]

    for (int c = 0; c < 8; c++) {
        const int kk = c * 64;

        // Prefetch X fp32 tile (128 x 64) into regs (overlaps prev compute)
        float4 xv[8];
#pragma unroll
        for (int i = 0; i < 8; i++) {
            const int idx = i * 256 + tid;
            const int row = idx >> 4;
            const int f4  = idx & 15;
            xv[i] = *(const float4*)(x + (m0 + row) * HH + kk + f4 * 4);
        }

        __syncthreads();   // prev chunk's ldmatrix reads complete

        // X -> fp16 hi/lo into smem
#pragma unroll
        for (int i = 0; i < 8; i++) {
            const int idx = i * 256 + tid;
            const int row = idx >> 4;
            const int f4  = idx & 15;
            const uint32_t bo = row * RSTRIDE + f4 * 8;
            float v0 = xv[i].x, v1 = xv[i].y, v2 = xv[i].z, v3 = xv[i].w;
            __half2 h01 = __floats2half2_rn(v0, v1);
            __half2 h23 = __floats2half2_rn(v2, v3);
            float l0 = v0 - __half2float(__low2half(h01));
            float l1 = v1 - __half2float(__high2half(h01));
            float l2 = v2 - __half2float(__low2half(h23));
            float l3 = v3 - __half2float(__high2half(h23));
            __half2 lo01 = __floats2half2_rn(l0, l1);
            __half2 lo23 = __floats2half2_rn(l2, l3);
            unsigned long long hp, lp;
            asm("mov.b64 %0, {%1, %2};" : "=l"(hp)
                : "r"(*(unsigned int*)&h01), "r"(*(unsigned int*)&h23));
            asm("mov.b64 %0, {%1, %2};" : "=l"(lp)
                : "r"(*(unsigned int*)&lo01), "r"(*(unsigned int*)&lo23));
            *(unsigned long long*)(smem + SM_XHI + bo) = hp;
            *(unsigned long long*)(smem + SM_XLO + bo) = lp;
        }

        // W tile (128 n-rows x 64 k) fp16 — L2-hot
#pragma unroll
        for (int i = 0; i < 4; i++) {
            const int g  = i * 256 + tid;      // uint4 index, 1024 total
            const int row = g >> 3;
            const int cc  = g & 7;
            const uint32_t bo = row * RSTRIDE + cc * 16;
            const size_t gi = (size_t)(n0 + row) * 64 + (kk >> 3) + cc;
            *(uint4*)(smem + SM_WHI + bo) = wh4[gi];
        }

        __syncthreads();

        // 4 k-steps; B frags shared across both X terms
#pragma unroll
        for (int ks = 0; ks < 4; ks++) {
            uint32_t Bv[16];
#pragma unroll
            for (int jp = 0; jp < 4; jp++)
                LDSM_X4(&Bv[jp * 4], bwhi + jp * 16 * RSTRIDE + ks * 32);
            uint32_t A0h[4], A1h[4], A0l[4], A1l[4];
            LDSM_X4(A0h, axhi + ks * 32);
            LDSM_X4(A1h, axhi + 16 * RSTRIDE + ks * 32);
            LDSM_X4(A0l, axlo + ks * 32);
            LDSM_X4(A1l, axlo + 16 * RSTRIDE + ks * 32);
#pragma unroll
            for (int nt = 0; nt < 8; nt++) {
                const int bi = (nt >> 1) * 4 + (nt & 1) * 2;
                HMMA16816(acc[0][nt], A0h, Bv[bi], Bv[bi + 1]);
                HMMA16816(acc[0][nt], A0l, Bv[bi], Bv[bi + 1]);
            }
#pragma unroll
            for (int nt = 0; nt < 8; nt++) {
                const int bi = (nt >> 1) * 4 + (nt & 1) * 2;
                HMMA16816(acc[1][nt], A1h, Bv[bi], Bv[bi + 1]);
                HMMA16816(acc[1][nt], A1l, Bv[bi], Bv[bi + 1]);
            }
        }
    }

    // Epilogue: s = sum_cols q[col]*tanh(D) per owned row
    float s[2][2] = {{0.f, 0.f}, {0.f, 0.f}};
#pragma unroll
    for (int mt = 0; mt < 2; mt++)
#pragma unroll
        for (int nt = 0; nt < 8; nt++) {
            const int col = warp_n * 64 + nt * 8 + 2 * (lane & 3);
            const float q0 = sq[col], q1 = sq[col + 1];
            s[mt][0] = fmaf(q0, fast_tanh(acc[mt][nt][0]),
                       fmaf(q1, fast_tanh(acc[mt][nt][1]), s[mt][0]));
            s[mt][1] = fmaf(q0, fast_tanh(acc[mt][nt][2]),
                       fmaf(q1, fast_tanh(acc[mt][nt][3]), s[mt][1]));
        }
#pragma unroll
    for (int mt = 0; mt < 2; mt++)
#pragma unroll
        for (int rh = 0; rh < 2; rh++) {
            float v = s[mt][rh];
            v += __shfl_xor_sync(0xffffffffu, v, 1);
            v += __shfl_xor_sync(0xffffffffu, v, 2);
            s[mt][rh] = v;
        }

    __syncthreads();               // all ldmatrix done; reuse smem
    float* red = (float*)smem;     // [2 warp_n][128 rows]
    if ((lane & 3) == 0) {
#pragma unroll
        for (int mt = 0; mt < 2; mt++)
#pragma unroll
            for (int rh = 0; rh < 2; rh++)
                red[warp_n * 128 + warp_m * 32 + mt * 16 + rh * 8 + (lane >> 2)]
                    = s[mt][rh];
    }
    __syncthreads();
    if (tid < 128)
        g_ep[(size_t)blockIdx.y * BS + m0 + tid] = red[tid] + red[128 + tid];
}

// ---------------------------------------------------------------------------
// Kernel 2: per-batch  w_t = exp(e_t - max), inclusive prefix P_s, ip = 1/P_s
// ---------------------------------------------------------------------------
__global__ __launch_bounds__(256) void scan_kernel()
{
    __shared__ float se[SS];
    __shared__ float sr[256];
    const int b   = blockIdx.x;
    const int tid = threadIdx.x;
    const int base = b * SS;

    for (int i = tid; i < SS; i += 256)
        se[i] = g_ep[base + i] + g_ep[BS + base + i];
    __syncthreads();

    float m = -1e30f;
    for (int i = tid; i < SS; i += 256) m = fmaxf(m, se[i]);
    sr[tid] = m;
    __syncthreads();
    for (int o = 128; o; o >>= 1) {
        if (tid < o) sr[tid] = fmaxf(sr[tid], sr[tid + o]);
        __syncthreads();
    }
    const float M = sr[0];
    __syncthreads();

    const int j0 = tid * 8;
    float wloc[8];
    float run = 0.f;
#pragma unroll
    for (int j = 0; j < 8; j++) {
        wloc[j] = expf(se[j0 + j] - M);
        run += wloc[j];
    }
    sr[tid] = run;
    __syncthreads();
    for (int o = 1; o < 256; o <<= 1) {
        const float v = (tid >= o) ? sr[tid - o] : 0.f;
        __syncthreads();
        sr[tid] += v;
        __syncthreads();
    }
    float acc = sr[tid] - run;
#pragma unroll
    for (int j = 0; j < 8; j++) {
        acc += wloc[j];
        g_w [base + j0 + j] = wloc[j];
        g_ip[base + j0 + j] = 1.0f / acc;
    }
}

// ---------------------------------------------------------------------------
// Kernel 3a: chunk sums T[b,c,h] = sum_{t in chunk} w_t * x[b,t,h]
// grid (NC, B), 128 threads, thread owns float4 at h=tid*4 (full H per CTA).
// ---------------------------------------------------------------------------
__global__ __launch_bounds__(128) void chunk_kernel(const float* __restrict__ x)
{
    __shared__ float sw[CS];
    const int c = blockIdx.x;
    const int b = blockIdx.y;
    const int tbase = b * SS + c * CS;
    sw[threadIdx.x] = g_w[tbase + threadIdx.x];
    __syncthreads();

    const float4* xp = (const float4*)(x + (size_t)tbase * HH) + threadIdx.x;
    float4 s = make_float4(0.f, 0.f, 0.f, 0.f);
#pragma unroll 8
    for (int t = 0; t < CS; t++) {
        const float4 v = xp[t * (HH/4)];
        const float w = sw[t];
        s.x = fmaf(w, v.x, s.x);
        s.y = fmaf(w, v.y, s.y);
        s.z = fmaf(w, v.z, s.z);
        s.w = fmaf(w, v.w, s.w);
    }
    ((float4*)(g_chunk + (size_t)(b * NC + c) * HH))[threadIdx.x] = s;
}

// ---------------------------------------------------------------------------
// Kernel 3b: a[b,s,h] = (chunk-prefix + running sum) * ip[b,s]
// grid (NC, B), 128 threads, float4 per thread, streaming stores.
// ---------------------------------------------------------------------------
__global__ __launch_bounds__(128) void a_kernel(
    const float* __restrict__ x, float* __restrict__ a_out)
{
    __shared__ float sw[CS];
    __shared__ float sip[CS];
    const int c = blockIdx.x;
    const int b = blockIdx.y;
    const int tbase = b * SS + c * CS;
    sw [threadIdx.x] = g_w [tbase + threadIdx.x];
    sip[threadIdx.x] = g_ip[tbase + threadIdx.x];
    __syncthreads();

    float4 acc = make_float4(0.f, 0.f, 0.f, 0.f);
    for (int cp = 0; cp < c; cp++) {
        const float4 t = ((const float4*)(g_chunk + (size_t)(b * NC + cp) * HH))[threadIdx.x];
        acc.x += t.x; acc.y += t.y; acc.z += t.z; acc.w += t.w;
    }

    const float4* xp = (const float4*)(x + (size_t)tbase * HH) + threadIdx.x;
    float4* op = (float4*)(a_out + (size_t)tbase * HH) + threadIdx.x;
#pragma unroll 4
    for (int t = 0; t < CS; t++) {
        const float4 v = xp[t * (HH/4)];
        const float w = sw[t];
        acc.x = fmaf(w, v.x, acc.x);
        acc.y = fmaf(w, v.y, acc.y);
        acc.z = fmaf(w, v.z, acc.z);
        acc.w = fmaf(w, v.w, acc.w);
        const float ip = sip[t];
        __stcs(op + t * (HH/4),
               make_float4(acc.x * ip, acc.y * ip, acc.z * ip, acc.w * ip));
    }
}

// ---------------------------------------------------------------------------
// Kernel 4: d[b,s,t] = (t<=s) ? w[b,t]*ip[b,s] : 0  — streaming stores
// ---------------------------------------------------------------------------
__global__ __launch_bounds__(256) void d_kernel(float* __restrict__ dd)
{
    const int row = blockIdx.x;
    const int b = row >> 11;
    const int s = row & (SS - 1);
    const float ip = g_ip[row];
    const float4* w4 = (const float4*)(g_w + ((size_t)b << 11));
    float4* o4 = (float4*)(dd + (size_t)row * SS);

#pragma unroll
    for (int it = 0; it < 2; it++) {
        const int i = it * 256 + threadIdx.x;
        const int t0 = i * 4;
        float4 r;
        if (t0 + 3 <= s) {
            const float4 wv = w4[i];
            r.x = wv.x * ip; r.y = wv.y * ip; r.z = wv.z * ip; r.w = wv.w * ip;
        } else if (t0 > s) {
            r.x = r.y = r.z = r.w = 0.f;
        } else {
            const float4 wv = w4[i];
            r.x = (t0     <= s) ? wv.x * ip : 0.f;
            r.y = (t0 + 1 <= s) ? wv.y * ip : 0.f;
            r.z = (t0 + 2 <= s) ? wv.z * ip : 0.f;
            r.w = (t0 + 3 <= s) ? wv.w * ip : 0.f;
        }
        __stcs(o4 + i, r);
    }
}

// ---------------------------------------------------------------------------
extern "C" void kernel_launch(void* const* d_in, const int* in_sizes, int n_in,
                              void* d_out, int out_size)
{
    const float* x = (const float*)d_in[0];   // [B,S,H]
    const float* W = (const float*)d_in[1];   // [A,H]
    const float* q = (const float*)d_in[2];   // [1,A]
    float* a_out = (float*)d_out;             // [B,S,1,H]
    float* dd    = (float*)d_out + A_ELEMS;   // [B,S,1,S]

    cudaFuncSetAttribute(e_mma_kernel,
                         cudaFuncAttributeMaxDynamicSharedMemorySize, SM_TOTAL);

    wsplit_kernel<<<AA * HH / 512, 256>>>(W);
    e_mma_kernel <<<dim3(BS / 128, 2), 256, SM_TOTAL>>>(x, q);
    scan_kernel  <<<BB, 256>>>();
    chunk_kernel <<<dim3(NC, BB), 128>>>(x);
    a_kernel     <<<dim3(NC, BB), 128>>>(x, a_out);
    d_kernel     <<<BS, 256>>>(dd);
}

// round 5
// speedup vs baseline: 1.9773x; 1.1502x over previous
#include <cuda_runtime.h>
#include <cuda_fp16.h>
#include <cstdint>

// Problem constants
#define BB 16
#define SS 2048
#define HH 512
#define AA 256
#define BS (BB*SS)               // 32768 tokens
#define A_ELEMS ((size_t)BS*HH)  // offset of d in output

// Scratch (device globals — no allocation allowed)
__device__ float g_ep[2*BS];     // per-n-half partial e
__device__ float g_w[BS];
__device__ float g_ip[BS];
#define NC 64
#define CS 32
__device__ float g_chunk[BB*NC*HH];     // 2 MB
__device__ float g_chunkpre[BB*NC*HH];  // 2 MB (exclusive prefix)
// W as fp16 pairs (uint32 = half2), [256 rows][256 pairs]
__device__ unsigned int g_wh[AA*HH/2];

// ---------------------------------------------------------------------------
__device__ __forceinline__ uint32_t smem_u32(const void* p) {
    uint32_t a;
    asm("{ .reg .u64 t; cvta.to.shared.u64 t, %1; cvt.u32.u64 %0, t; }"
        : "=r"(a) : "l"(p));
    return a;
}

#define LDSM_X4(r, addr) \
    asm volatile("ldmatrix.sync.aligned.m8n8.x4.shared.b16 {%0,%1,%2,%3}, [%4];" \
        : "=r"((r)[0]), "=r"((r)[1]), "=r"((r)[2]), "=r"((r)[3]) : "r"(addr))

#define HMMA16816(d, a, b0, b1) \
    asm volatile("mma.sync.aligned.m16n8k16.row.col.f32.f16.f16.f32 " \
        "{%0,%1,%2,%3},{%4,%5,%6,%7},{%8,%9},{%0,%1,%2,%3};" \
        : "+f"((d)[0]), "+f"((d)[1]), "+f"((d)[2]), "+f"((d)[3]) \
        : "r"((a)[0]), "r"((a)[1]), "r"((a)[2]), "r"((a)[3]), "r"(b0), "r"(b1))

__device__ __forceinline__ float fast_tanh(float v) {
    float t; asm("ex2.approx.f32 %0, %1;" : "=f"(t) : "f"(v * 2.885390081777927f));
    float r; asm("rcp.approx.f32 %0, %1;" : "=f"(r) : "f"(t + 1.0f));
    return fmaf(-2.0f, r, 1.0f);   // tanh(v) = 1 - 2/(e^{2v}+1)
}

// ---------------------------------------------------------------------------
// Kernel 0: W [256,512] fp32 -> fp16 pairs
// ---------------------------------------------------------------------------
__global__ __launch_bounds__(256) void wsplit_kernel(const float* __restrict__ W)
{
    const int i = blockIdx.x * 256 + threadIdx.x;   // pair index
    const float2 v = ((const float2*)W)[i];
    __half2 hp = __floats2half2_rn(v.x, v.y);
    g_wh[i] = *(unsigned int*)&hp;
}

// ---------------------------------------------------------------------------
// Kernel 1: e-partial via mma.sync fp16, 2-term X split (xh + xl), W fp16.
// CTA tile: M=128 tokens x N=128 A-cols (blockIdx.y), K chunks of 64.
// 8 warps 4(m) x 2(n); warp tile 32x64.
// ---------------------------------------------------------------------------
#define RSTRIDE 144              // bytes per smem row (64 fp16 + pad)
#define SM_XHI  0
#define SM_XLO  18432
#define SM_WHI  36864
#define SM_Q    55296
#define SM_TOTAL 55808

__global__ __launch_bounds__(256, 2) void e_mma_kernel(
    const float* __restrict__ x, const float* __restrict__ q)
{
    extern __shared__ __align__(128) char smem[];
    const uint32_t sb = smem_u32(smem);
    const int tid  = threadIdx.x;
    const int lane = tid & 31;
    const int warp = tid >> 5;
    const int warp_m = warp & 3;
    const int warp_n = warp >> 2;
    const size_t m0 = (size_t)blockIdx.x * 128;
    const int n0 = blockIdx.y * 128;

    float* sq = (float*)(smem + SM_Q);
    if (tid < 128) sq[tid] = q[n0 + tid];

    float acc[2][8][4];
#pragma unroll
    for (int mt = 0; mt < 2; mt++)
#pragma unroll
        for (int nt = 0; nt < 8; nt++)
#pragma unroll
            for (int j = 0; j < 4; j++) acc[mt][nt][j] = 0.f;

    // per-lane ldmatrix address offsets (bytes)
    const uint32_t a_off = (lane & 15) * RSTRIDE + ((lane >> 4) << 4);
    const uint32_t b_off = ((((lane >> 4) & 1) << 3) + (lane & 7)) * RSTRIDE
                         + (((lane >> 3) & 1) << 4);
    const uint32_t axhi = sb + SM_XHI + warp_m * 32 * RSTRIDE + a_off;
    const uint32_t axlo = axhi + (SM_XLO - SM_XHI);
    const uint32_t bwhi = sb + SM_WHI + warp_n * 64 * RSTRIDE + b_off;

    const uint4* wh4 = (const uint4*)g_wh;   // [a][64 uint4 per row]

    for (int c = 0; c < 8; c++) {
        const int kk = c * 64;

        // Prefetch X fp32 tile (128 x 64) into regs (overlaps prev compute)
        float4 xv[8];
#pragma unroll
        for (int i = 0; i < 8; i++) {
            const int idx = i * 256 + tid;
            const int row = idx >> 4;
            const int f4  = idx & 15;
            xv[i] = *(const float4*)(x + (m0 + row) * HH + kk + f4 * 4);
        }

        __syncthreads();   // prev chunk's ldmatrix reads complete

        // X -> fp16 hi/lo into smem
#pragma unroll
        for (int i = 0; i < 8; i++) {
            const int idx = i * 256 + tid;
            const int row = idx >> 4;
            const int f4  = idx & 15;
            const uint32_t bo = row * RSTRIDE + f4 * 8;
            float v0 = xv[i].x, v1 = xv[i].y, v2 = xv[i].z, v3 = xv[i].w;
            __half2 h01 = __floats2half2_rn(v0, v1);
            __half2 h23 = __floats2half2_rn(v2, v3);
            float l0 = v0 - __half2float(__low2half(h01));
            float l1 = v1 - __half2float(__high2half(h01));
            float l2 = v2 - __half2float(__low2half(h23));
            float l3 = v3 - __half2float(__high2half(h23));
            __half2 lo01 = __floats2half2_rn(l0, l1);
            __half2 lo23 = __floats2half2_rn(l2, l3);
            unsigned long long hp, lp;
            asm("mov.b64 %0, {%1, %2};" : "=l"(hp)
                : "r"(*(unsigned int*)&h01), "r"(*(unsigned int*)&h23));
            asm("mov.b64 %0, {%1, %2};" : "=l"(lp)
                : "r"(*(unsigned int*)&lo01), "r"(*(unsigned int*)&lo23));
            *(unsigned long long*)(smem + SM_XHI + bo) = hp;
            *(unsigned long long*)(smem + SM_XLO + bo) = lp;
        }

        // W tile (128 n-rows x 64 k) fp16 — L2-hot
#pragma unroll
        for (int i = 0; i < 4; i++) {
            const int g  = i * 256 + tid;      // uint4 index, 1024 total
            const int row = g >> 3;
            const int cc  = g & 7;
            const uint32_t bo = row * RSTRIDE + cc * 16;
            const size_t gi = (size_t)(n0 + row) * 64 + (kk >> 3) + cc;
            *(uint4*)(smem + SM_WHI + bo) = wh4[gi];
        }

        __syncthreads();

        // 4 k-steps; B frags shared across both X terms
#pragma unroll
        for (int ks = 0; ks < 4; ks++) {
            uint32_t Bv[16];
#pragma unroll
            for (int jp = 0; jp < 4; jp++)
                LDSM_X4(&Bv[jp * 4], bwhi + jp * 16 * RSTRIDE + ks * 32);
            uint32_t A0h[4], A1h[4], A0l[4], A1l[4];
            LDSM_X4(A0h, axhi + ks * 32);
            LDSM_X4(A1h, axhi + 16 * RSTRIDE + ks * 32);
            LDSM_X4(A0l, axlo + ks * 32);
            LDSM_X4(A1l, axlo + 16 * RSTRIDE + ks * 32);
#pragma unroll
            for (int nt = 0; nt < 8; nt++) {
                const int bi = (nt >> 1) * 4 + (nt & 1) * 2;
                HMMA16816(acc[0][nt], A0h, Bv[bi], Bv[bi + 1]);
                HMMA16816(acc[0][nt], A0l, Bv[bi], Bv[bi + 1]);
            }
#pragma unroll
            for (int nt = 0; nt < 8; nt++) {
                const int bi = (nt >> 1) * 4 + (nt & 1) * 2;
                HMMA16816(acc[1][nt], A1h, Bv[bi], Bv[bi + 1]);
                HMMA16816(acc[1][nt], A1l, Bv[bi], Bv[bi + 1]);
            }
        }
    }

    // Epilogue: s = sum_cols q[col]*tanh(D) per owned row
    float s[2][2] = {{0.f, 0.f}, {0.f, 0.f}};
#pragma unroll
    for (int mt = 0; mt < 2; mt++)
#pragma unroll
        for (int nt = 0; nt < 8; nt++) {
            const int col = warp_n * 64 + nt * 8 + 2 * (lane & 3);
            const float q0 = sq[col], q1 = sq[col + 1];
            s[mt][0] = fmaf(q0, fast_tanh(acc[mt][nt][0]),
                       fmaf(q1, fast_tanh(acc[mt][nt][1]), s[mt][0]));
            s[mt][1] = fmaf(q0, fast_tanh(acc[mt][nt][2]),
                       fmaf(q1, fast_tanh(acc[mt][nt][3]), s[mt][1]));
        }
#pragma unroll
    for (int mt = 0; mt < 2; mt++)
#pragma unroll
        for (int rh = 0; rh < 2; rh++) {
            float v = s[mt][rh];
            v += __shfl_xor_sync(0xffffffffu, v, 1);
            v += __shfl_xor_sync(0xffffffffu, v, 2);
            s[mt][rh] = v;
        }

    __syncthreads();               // all ldmatrix done; reuse smem
    float* red = (float*)smem;     // [2 warp_n][128 rows]
    if ((lane & 3) == 0) {
#pragma unroll
        for (int mt = 0; mt < 2; mt++)
#pragma unroll
            for (int rh = 0; rh < 2; rh++)
                red[warp_n * 128 + warp_m * 32 + mt * 16 + rh * 8 + (lane >> 2)]
                    = s[mt][rh];
    }
    __syncthreads();
    if (tid < 128)
        g_ep[(size_t)blockIdx.y * BS + m0 + tid] = red[tid] + red[128 + tid];
}

// ---------------------------------------------------------------------------
// Kernel 2: per-batch  w_t = exp(e_t - max), inclusive prefix P_s, ip = 1/P_s
// ---------------------------------------------------------------------------
__global__ __launch_bounds__(256) void scan_kernel()
{
    __shared__ float se[SS];
    __shared__ float sr[256];
    const int b   = blockIdx.x;
    const int tid = threadIdx.x;
    const int base = b * SS;

    for (int i = tid; i < SS; i += 256)
        se[i] = g_ep[base + i] + g_ep[BS + base + i];
    __syncthreads();

    float m = -1e30f;
    for (int i = tid; i < SS; i += 256) m = fmaxf(m, se[i]);
    sr[tid] = m;
    __syncthreads();
    for (int o = 128; o; o >>= 1) {
        if (tid < o) sr[tid] = fmaxf(sr[tid], sr[tid + o]);
        __syncthreads();
    }
    const float M = sr[0];
    __syncthreads();

    const int j0 = tid * 8;
    float wloc[8];
    float run = 0.f;
#pragma unroll
    for (int j = 0; j < 8; j++) {
        wloc[j] = expf(se[j0 + j] - M);
        run += wloc[j];
    }
    sr[tid] = run;
    __syncthreads();
    for (int o = 1; o < 256; o <<= 1) {
        const float v = (tid >= o) ? sr[tid - o] : 0.f;
        __syncthreads();
        sr[tid] += v;
        __syncthreads();
    }
    float acc = sr[tid] - run;
#pragma unroll
    for (int j = 0; j < 8; j++) {
        acc += wloc[j];
        g_w [base + j0 + j] = wloc[j];
        g_ip[base + j0 + j] = 1.0f / acc;
    }
}

// ---------------------------------------------------------------------------
// Kernel 3a: chunk sums T[b,c,h] = sum_{t in chunk} w_t * x[b,t,h]
// grid (NC=64, B), 128 threads, thread owns float4 at h=tid*4.
// ---------------------------------------------------------------------------
__global__ __launch_bounds__(128) void chunk_kernel(const float* __restrict__ x)
{
    __shared__ float sw[CS];
    const int c = blockIdx.x;
    const int b = blockIdx.y;
    const int tbase = b * SS + c * CS;
    if (threadIdx.x < CS) sw[threadIdx.x] = g_w[tbase + threadIdx.x];
    __syncthreads();

    const float4* xp = (const float4*)(x + (size_t)tbase * HH) + threadIdx.x;
    float4 s = make_float4(0.f, 0.f, 0.f, 0.f);
#pragma unroll 8
    for (int t = 0; t < CS; t++) {
        const float4 v = xp[t * (HH/4)];
        const float w = sw[t];
        s.x = fmaf(w, v.x, s.x);
        s.y = fmaf(w, v.y, s.y);
        s.z = fmaf(w, v.z, s.z);
        s.w = fmaf(w, v.w, s.w);
    }
    ((float4*)(g_chunk + (size_t)(b * NC + c) * HH))[threadIdx.x] = s;
}

// ---------------------------------------------------------------------------
// Kernel 3p: exclusive prefix over chunks: pre[b,c,h] = sum_{c'<c} T[b,c',h]
// grid (B, H/128), 128 threads, thread owns one h; 64 serial steps (L2-hot).
// ---------------------------------------------------------------------------
__global__ __launch_bounds__(128) void chunkpre_kernel()
{
    const int b = blockIdx.x;
    const int h = blockIdx.y * 128 + threadIdx.x;
    float acc = 0.f;
#pragma unroll 4
    for (int c = 0; c < NC; c++) {
        const size_t idx = (size_t)(b * NC + c) * HH + h;
        const float v = g_chunk[idx];
        g_chunkpre[idx] = acc;
        acc += v;
    }
}

// ---------------------------------------------------------------------------
// Kernel 3b: a[b,s,h] = (chunkpre + running sum) * ip[b,s]
// grid (NC=64, B), 128 threads, float4 per thread, streaming stores.
// ---------------------------------------------------------------------------
__global__ __launch_bounds__(128) void a_kernel(
    const float* __restrict__ x, float* __restrict__ a_out)
{
    __shared__ float sw[CS];
    __shared__ float sip[CS];
    const int c = blockIdx.x;
    const int b = blockIdx.y;
    const int tbase = b * SS + c * CS;
    if (threadIdx.x < CS) {
        sw [threadIdx.x] = g_w [tbase + threadIdx.x];
        sip[threadIdx.x] = g_ip[tbase + threadIdx.x];
    }
    __syncthreads();

    float4 acc = ((const float4*)(g_chunkpre + (size_t)(b * NC + c) * HH))[threadIdx.x];

    const float4* xp = (const float4*)(x + (size_t)tbase * HH) + threadIdx.x;
    float4* op = (float4*)(a_out + (size_t)tbase * HH) + threadIdx.x;
#pragma unroll 8
    for (int t = 0; t < CS; t++) {
        const float4 v = xp[t * (HH/4)];
        const float w = sw[t];
        acc.x = fmaf(w, v.x, acc.x);
        acc.y = fmaf(w, v.y, acc.y);
        acc.z = fmaf(w, v.z, acc.z);
        acc.w = fmaf(w, v.w, acc.w);
        const float ip = sip[t];
        __stcs(op + t * (HH/4),
               make_float4(acc.x * ip, acc.y * ip, acc.z * ip, acc.w * ip));
    }
}

// ---------------------------------------------------------------------------
// Kernel 4: d[b,s,t] = (t<=s) ? w[b,t]*ip[b,s] : 0  — streaming stores
// ---------------------------------------------------------------------------
__global__ __launch_bounds__(256) void d_kernel(float* __restrict__ dd)
{
    const int row = blockIdx.x;
    const int b = row >> 11;
    const int s = row & (SS - 1);
    const float ip = g_ip[row];
    const float4* w4 = (const float4*)(g_w + ((size_t)b << 11));
    float4* o4 = (float4*)(dd + (size_t)row * SS);

#pragma unroll
    for (int it = 0; it < 2; it++) {
        const int i = it * 256 + threadIdx.x;
        const int t0 = i * 4;
        float4 r;
        if (t0 + 3 <= s) {
            const float4 wv = w4[i];
            r.x = wv.x * ip; r.y = wv.y * ip; r.z = wv.z * ip; r.w = wv.w * ip;
        } else if (t0 > s) {
            r.x = r.y = r.z = r.w = 0.f;
        } else {
            const float4 wv = w4[i];
            r.x = (t0     <= s) ? wv.x * ip : 0.f;
            r.y = (t0 + 1 <= s) ? wv.y * ip : 0.f;
            r.z = (t0 + 2 <= s) ? wv.z * ip : 0.f;
            r.w = (t0 + 3 <= s) ? wv.w * ip : 0.f;
        }
        __stcs(o4 + i, r);
    }
}

// ---------------------------------------------------------------------------
extern "C" void kernel_launch(void* const* d_in, const int* in_sizes, int n_in,
                              void* d_out, int out_size)
{
    const float* x = (const float*)d_in[0];   // [B,S,H]
    const float* W = (const float*)d_in[1];   // [A,H]
    const float* q = (const float*)d_in[2];   // [1,A]
    float* a_out = (float*)d_out;             // [B,S,1,H]
    float* dd    = (float*)d_out + A_ELEMS;   // [B,S,1,S]

    cudaFuncSetAttribute(e_mma_kernel,
                         cudaFuncAttributeMaxDynamicSharedMemorySize, SM_TOTAL);

    wsplit_kernel  <<<AA * HH / 512, 256>>>(W);
    e_mma_kernel   <<<dim3(BS / 128, 2), 256, SM_TOTAL>>>(x, q);
    scan_kernel    <<<BB, 256>>>();
    chunk_kernel   <<<dim3(NC, BB), 128>>>(x);
    chunkpre_kernel<<<dim3(BB, HH / 128), 128>>>();
    a_kernel       <<<dim3(NC, BB), 128>>>(x, a_out);
    d_kernel       <<<BS, 256>>>(dd);
}

// round 6
// speedup vs baseline: 2.1396x; 1.0821x over previous
#include <cuda_runtime.h>
#include <cuda_fp16.h>
#include <cstdint>

// Problem constants
#define BB 16
#define SS 2048
#define HH 512
#define AA 256
#define BS (BB*SS)               // 32768 tokens
#define A_ELEMS ((size_t)BS*HH)  // offset of d in output

// Scratch (device globals — no allocation allowed)
__device__ float g_ep[2*BS];     // per-n-half partial e
__device__ float g_w[BS];
__device__ float g_ip[BS];
#define NC 128
#define CS 16
__device__ float g_chunk[BB*NC*HH];     // 4 MB
__device__ float g_chunkpre[BB*NC*HH];  // 4 MB (exclusive prefix)
// W as fp16 pairs (uint32 = half2), [256 rows][256 pairs]
__device__ unsigned int g_wh[AA*HH/2];

// ---------------------------------------------------------------------------
__device__ __forceinline__ uint32_t smem_u32(const void* p) {
    uint32_t a;
    asm("{ .reg .u64 t; cvta.to.shared.u64 t, %1; cvt.u32.u64 %0, t; }"
        : "=r"(a) : "l"(p));
    return a;
}

#define LDSM_X4(r, addr) \
    asm volatile("ldmatrix.sync.aligned.m8n8.x4.shared.b16 {%0,%1,%2,%3}, [%4];" \
        : "=r"((r)[0]), "=r"((r)[1]), "=r"((r)[2]), "=r"((r)[3]) : "r"(addr))

#define HMMA16816(d, a, b0, b1) \
    asm volatile("mma.sync.aligned.m16n8k16.row.col.f32.f16.f16.f32 " \
        "{%0,%1,%2,%3},{%4,%5,%6,%7},{%8,%9},{%0,%1,%2,%3};" \
        : "+f"((d)[0]), "+f"((d)[1]), "+f"((d)[2]), "+f"((d)[3]) \
        : "r"((a)[0]), "r"((a)[1]), "r"((a)[2]), "r"((a)[3]), "r"(b0), "r"(b1))

__device__ __forceinline__ float fast_tanh(float v) {
    float t; asm("ex2.approx.f32 %0, %1;" : "=f"(t) : "f"(v * 2.885390081777927f));
    float r; asm("rcp.approx.f32 %0, %1;" : "=f"(r) : "f"(t + 1.0f));
    return fmaf(-2.0f, r, 1.0f);   // tanh(v) = 1 - 2/(e^{2v}+1)
}

// ---------------------------------------------------------------------------
// Kernel 0: W [256,512] fp32 -> fp16 pairs
// ---------------------------------------------------------------------------
__global__ __launch_bounds__(256) void wsplit_kernel(const float* __restrict__ W)
{
    const int i = blockIdx.x * 256 + threadIdx.x;   // pair index
    const float2 v = ((const float2*)W)[i];
    __half2 hp = __floats2half2_rn(v.x, v.y);
    g_wh[i] = *(unsigned int*)&hp;
}

// ---------------------------------------------------------------------------
// Kernel 1: e-partial via mma.sync fp16 (single term, X and W both fp16).
// CTA tile: M=128 tokens x N=128 A-cols (blockIdx.y), K chunks of 64.
// 8 warps 4(m) x 2(n); warp tile 32x64.
// ---------------------------------------------------------------------------
#define RSTRIDE 144              // bytes per smem row (64 fp16 + pad)
#define SM_XHI  0
#define SM_WHI  18432
#define SM_Q    36864
#define SM_TOTAL 37376

__global__ __launch_bounds__(256, 2) void e_mma_kernel(
    const float* __restrict__ x, const float* __restrict__ q)
{
    extern __shared__ __align__(128) char smem[];
    const uint32_t sb = smem_u32(smem);
    const int tid  = threadIdx.x;
    const int lane = tid & 31;
    const int warp = tid >> 5;
    const int warp_m = warp & 3;
    const int warp_n = warp >> 2;
    const size_t m0 = (size_t)blockIdx.x * 128;
    const int n0 = blockIdx.y * 128;

    float* sq = (float*)(smem + SM_Q);
    if (tid < 128) sq[tid] = q[n0 + tid];

    float acc[2][8][4];
#pragma unroll
    for (int mt = 0; mt < 2; mt++)
#pragma unroll
        for (int nt = 0; nt < 8; nt++)
#pragma unroll
            for (int j = 0; j < 4; j++) acc[mt][nt][j] = 0.f;

    // per-lane ldmatrix address offsets (bytes)
    const uint32_t a_off = (lane & 15) * RSTRIDE + ((lane >> 4) << 4);
    const uint32_t b_off = ((((lane >> 4) & 1) << 3) + (lane & 7)) * RSTRIDE
                         + (((lane >> 3) & 1) << 4);
    const uint32_t axhi = sb + SM_XHI + warp_m * 32 * RSTRIDE + a_off;
    const uint32_t bwhi = sb + SM_WHI + warp_n * 64 * RSTRIDE + b_off;

    const uint4* wh4 = (const uint4*)g_wh;   // [a][64 uint4 per row]

    for (int c = 0; c < 8; c++) {
        const int kk = c * 64;

        // Prefetch X fp32 tile (128 x 64) into regs (overlaps prev compute)
        float4 xv[8];
#pragma unroll
        for (int i = 0; i < 8; i++) {
            const int idx = i * 256 + tid;
            const int row = idx >> 4;
            const int f4  = idx & 15;
            xv[i] = *(const float4*)(x + (m0 + row) * HH + kk + f4 * 4);
        }

        __syncthreads();   // prev chunk's ldmatrix reads complete

        // X -> fp16 into smem
#pragma unroll
        for (int i = 0; i < 8; i++) {
            const int idx = i * 256 + tid;
            const int row = idx >> 4;
            const int f4  = idx & 15;
            const uint32_t bo = row * RSTRIDE + f4 * 8;
            __half2 h01 = __floats2half2_rn(xv[i].x, xv[i].y);
            __half2 h23 = __floats2half2_rn(xv[i].z, xv[i].w);
            unsigned long long hp;
            asm("mov.b64 %0, {%1, %2};" : "=l"(hp)
                : "r"(*(unsigned int*)&h01), "r"(*(unsigned int*)&h23));
            *(unsigned long long*)(smem + SM_XHI + bo) = hp;
        }

        // W tile (128 n-rows x 64 k) fp16 — L2-hot
#pragma unroll
        for (int i = 0; i < 4; i++) {
            const int g  = i * 256 + tid;      // uint4 index, 1024 total
            const int row = g >> 3;
            const int cc  = g & 7;
            const uint32_t bo = row * RSTRIDE + cc * 16;
            const size_t gi = (size_t)(n0 + row) * 64 + (kk >> 3) + cc;
            *(uint4*)(smem + SM_WHI + bo) = wh4[gi];
        }

        __syncthreads();

        // 4 k-steps
#pragma unroll
        for (int ks = 0; ks < 4; ks++) {
            uint32_t Bv[16];
#pragma unroll
            for (int jp = 0; jp < 4; jp++)
                LDSM_X4(&Bv[jp * 4], bwhi + jp * 16 * RSTRIDE + ks * 32);
            uint32_t A0h[4], A1h[4];
            LDSM_X4(A0h, axhi + ks * 32);
            LDSM_X4(A1h, axhi + 16 * RSTRIDE + ks * 32);
#pragma unroll
            for (int nt = 0; nt < 8; nt++) {
                const int bi = (nt >> 1) * 4 + (nt & 1) * 2;
                HMMA16816(acc[0][nt], A0h, Bv[bi], Bv[bi + 1]);
            }
#pragma unroll
            for (int nt = 0; nt < 8; nt++) {
                const int bi = (nt >> 1) * 4 + (nt & 1) * 2;
                HMMA16816(acc[1][nt], A1h, Bv[bi], Bv[bi + 1]);
            }
        }
    }

    // Epilogue: s = sum_cols q[col]*tanh(D) per owned row
    float s[2][2] = {{0.f, 0.f}, {0.f, 0.f}};
#pragma unroll
    for (int mt = 0; mt < 2; mt++)
#pragma unroll
        for (int nt = 0; nt < 8; nt++) {
            const int col = warp_n * 64 + nt * 8 + 2 * (lane & 3);
            const float q0 = sq[col], q1 = sq[col + 1];
            s[mt][0] = fmaf(q0, fast_tanh(acc[mt][nt][0]),
                       fmaf(q1, fast_tanh(acc[mt][nt][1]), s[mt][0]));
            s[mt][1] = fmaf(q0, fast_tanh(acc[mt][nt][2]),
                       fmaf(q1, fast_tanh(acc[mt][nt][3]), s[mt][1]));
        }
#pragma unroll
    for (int mt = 0; mt < 2; mt++)
#pragma unroll
        for (int rh = 0; rh < 2; rh++) {
            float v = s[mt][rh];
            v += __shfl_xor_sync(0xffffffffu, v, 1);
            v += __shfl_xor_sync(0xffffffffu, v, 2);
            s[mt][rh] = v;
        }

    __syncthreads();               // all ldmatrix done; reuse smem
    float* red = (float*)smem;     // [2 warp_n][128 rows]
    if ((lane & 3) == 0) {
#pragma unroll
        for (int mt = 0; mt < 2; mt++)
#pragma unroll
            for (int rh = 0; rh < 2; rh++)
                red[warp_n * 128 + warp_m * 32 + mt * 16 + rh * 8 + (lane >> 2)]
                    = s[mt][rh];
    }
    __syncthreads();
    if (tid < 128)
        g_ep[(size_t)blockIdx.y * BS + m0 + tid] = red[tid] + red[128 + tid];
}

// ---------------------------------------------------------------------------
// Kernel 2: per-batch  w_t = exp(e_t - max), inclusive prefix P_s, ip = 1/P_s
// ---------------------------------------------------------------------------
__global__ __launch_bounds__(256) void scan_kernel()
{
    __shared__ float se[SS];
    __shared__ float sr[256];
    const int b   = blockIdx.x;
    const int tid = threadIdx.x;
    const int base = b * SS;

    for (int i = tid; i < SS; i += 256)
        se[i] = g_ep[base + i] + g_ep[BS + base + i];
    __syncthreads();

    float m = -1e30f;
    for (int i = tid; i < SS; i += 256) m = fmaxf(m, se[i]);
    sr[tid] = m;
    __syncthreads();
    for (int o = 128; o; o >>= 1) {
        if (tid < o) sr[tid] = fmaxf(sr[tid], sr[tid + o]);
        __syncthreads();
    }
    const float M = sr[0];
    __syncthreads();

    const int j0 = tid * 8;
    float wloc[8];
    float run = 0.f;
#pragma unroll
    for (int j = 0; j < 8; j++) {
        wloc[j] = expf(se[j0 + j] - M);
        run += wloc[j];
    }
    sr[tid] = run;
    __syncthreads();
    for (int o = 1; o < 256; o <<= 1) {
        const float v = (tid >= o) ? sr[tid - o] : 0.f;
        __syncthreads();
        sr[tid] += v;
        __syncthreads();
    }
    float acc = sr[tid] - run;
#pragma unroll
    for (int j = 0; j < 8; j++) {
        acc += wloc[j];
        g_w [base + j0 + j] = wloc[j];
        g_ip[base + j0 + j] = 1.0f / acc;
    }
}

// ---------------------------------------------------------------------------
// Kernel 3a: chunk sums T[b,c,h] = sum_{t in chunk} w_t * x[b,t,h]
// grid (NC=128, B), 128 threads, thread owns float4 at h=tid*4.
// ---------------------------------------------------------------------------
__global__ __launch_bounds__(128) void chunk_kernel(const float* __restrict__ x)
{
    __shared__ float sw[CS];
    const int c = blockIdx.x;
    const int b = blockIdx.y;
    const int tbase = b * SS + c * CS;
    if (threadIdx.x < CS) sw[threadIdx.x] = g_w[tbase + threadIdx.x];
    __syncthreads();

    const float4* xp = (const float4*)(x + (size_t)tbase * HH) + threadIdx.x;
    float4 s = make_float4(0.f, 0.f, 0.f, 0.f);
#pragma unroll
    for (int t = 0; t < CS; t++) {
        const float4 v = xp[t * (HH/4)];
        const float w = sw[t];
        s.x = fmaf(w, v.x, s.x);
        s.y = fmaf(w, v.y, s.y);
        s.z = fmaf(w, v.z, s.z);
        s.w = fmaf(w, v.w, s.w);
    }
    ((float4*)(g_chunk + (size_t)(b * NC + c) * HH))[threadIdx.x] = s;
}

// ---------------------------------------------------------------------------
// Kernel 3p: exclusive prefix over chunks: pre[b,c,h] = sum_{c'<c} T[b,c',h]
// grid (B, H/128), 128 threads, thread owns one h; NC serial steps (L2-hot).
// ---------------------------------------------------------------------------
__global__ __launch_bounds__(128) void chunkpre_kernel()
{
    const int b = blockIdx.x;
    const int h = blockIdx.y * 128 + threadIdx.x;
    float acc = 0.f;
#pragma unroll 4
    for (int c = 0; c < NC; c++) {
        const size_t idx = (size_t)(b * NC + c) * HH + h;
        const float v = g_chunk[idx];
        g_chunkpre[idx] = acc;
        acc += v;
    }
}

// ---------------------------------------------------------------------------
// Kernel 3b: a[b,s,h] = (chunkpre + running sum) * ip[b,s]
// grid (NC=128, B), 128 threads, float4 per thread, streaming stores.
// ---------------------------------------------------------------------------
__global__ __launch_bounds__(128) void a_kernel(
    const float* __restrict__ x, float* __restrict__ a_out)
{
    __shared__ float sw[CS];
    __shared__ float sip[CS];
    const int c = blockIdx.x;
    const int b = blockIdx.y;
    const int tbase = b * SS + c * CS;
    if (threadIdx.x < CS) {
        sw [threadIdx.x] = g_w [tbase + threadIdx.x];
        sip[threadIdx.x] = g_ip[tbase + threadIdx.x];
    }
    __syncthreads();

    float4 acc = ((const float4*)(g_chunkpre + (size_t)(b * NC + c) * HH))[threadIdx.x];

    const float4* xp = (const float4*)(x + (size_t)tbase * HH) + threadIdx.x;
    float4* op = (float4*)(a_out + (size_t)tbase * HH) + threadIdx.x;
#pragma unroll
    for (int t = 0; t < CS; t++) {
        const float4 v = xp[t * (HH/4)];
        const float w = sw[t];
        acc.x = fmaf(w, v.x, acc.x);
        acc.y = fmaf(w, v.y, acc.y);
        acc.z = fmaf(w, v.z, acc.z);
        acc.w = fmaf(w, v.w, acc.w);
        const float ip = sip[t];
        __stcs(op + t * (HH/4),
               make_float4(acc.x * ip, acc.y * ip, acc.z * ip, acc.w * ip));
    }
}

// ---------------------------------------------------------------------------
// Kernel 4: d[b,s,t] = (t<=s) ? w[b,t]*ip[b,s] : 0  — streaming stores
// ---------------------------------------------------------------------------
__global__ __launch_bounds__(256) void d_kernel(float* __restrict__ dd)
{
    const int row = blockIdx.x;
    const int b = row >> 11;
    const int s = row & (SS - 1);
    const float ip = g_ip[row];
    const float4* w4 = (const float4*)(g_w + ((size_t)b << 11));
    float4* o4 = (float4*)(dd + (size_t)row * SS);

#pragma unroll
    for (int it = 0; it < 2; it++) {
        const int i = it * 256 + threadIdx.x;
        const int t0 = i * 4;
        float4 r;
        if (t0 + 3 <= s) {
            const float4 wv = w4[i];
            r.x = wv.x * ip; r.y = wv.y * ip; r.z = wv.z * ip; r.w = wv.w * ip;
        } else if (t0 > s) {
            r.x = r.y = r.z = r.w = 0.f;
        } else {
            const float4 wv = w4[i];
            r.x = (t0     <= s) ? wv.x * ip : 0.f;
            r.y = (t0 + 1 <= s) ? wv.y * ip : 0.f;
            r.z = (t0 + 2 <= s) ? wv.z * ip : 0.f;
            r.w = (t0 + 3 <= s) ? wv.w * ip : 0.f;
        }
        __stcs(o4 + i, r);
    }
}

// ---------------------------------------------------------------------------
extern "C" void kernel_launch(void* const* d_in, const int* in_sizes, int n_in,
                              void* d_out, int out_size)
{
    const float* x = (const float*)d_in[0];   // [B,S,H]
    const float* W = (const float*)d_in[1];   // [A,H]
    const float* q = (const float*)d_in[2];   // [1,A]
    float* a_out = (float*)d_out;             // [B,S,1,H]
    float* dd    = (float*)d_out + A_ELEMS;   // [B,S,1,S]

    cudaFuncSetAttribute(e_mma_kernel,
                         cudaFuncAttributeMaxDynamicSharedMemorySize, SM_TOTAL);

    wsplit_kernel  <<<AA * HH / 512, 256>>>(W);
    e_mma_kernel   <<<dim3(BS / 128, 2), 256, SM_TOTAL>>>(x, q);
    scan_kernel    <<<BB, 256>>>();
    chunk_kernel   <<<dim3(NC, BB), 128>>>(x);
    chunkpre_kernel<<<dim3(BB, HH / 128), 128>>>();
    a_kernel       <<<dim3(NC, BB), 128>>>(x, a_out);
    d_kernel       <<<BS, 256>>>(dd);
}

// round 7
// speedup vs baseline: 2.1935x; 1.0252x over previous
#include <cuda_runtime.h>
#include <cuda_fp16.h>
#include <cstdint>

// Problem constants
#define BB 16
#define SS 2048
#define HH 512
#define AA 256
#define BS (BB*SS)               // 32768 tokens
#define A_ELEMS ((size_t)BS*HH)  // offset of d in output

// Scratch (device globals — no allocation allowed)
__device__ float g_e[BS];
__device__ float g_w[BS];
__device__ float g_ip[BS];
#define NC 128
#define CS 16
__device__ float g_chunk[BB*NC*HH];     // 4 MB
__device__ float g_chunkpre[BB*NC*HH];  // 4 MB (exclusive prefix)
// W as fp16 pairs (uint32 = half2), [256 rows][256 pairs]
__device__ unsigned int g_wh[AA*HH/2];

// ---------------------------------------------------------------------------
__device__ __forceinline__ uint32_t smem_u32(const void* p) {
    uint32_t a;
    asm("{ .reg .u64 t; cvta.to.shared.u64 t, %1; cvt.u32.u64 %0, t; }"
        : "=r"(a) : "l"(p));
    return a;
}

#define LDSM_X4(r, addr) \
    asm volatile("ldmatrix.sync.aligned.m8n8.x4.shared.b16 {%0,%1,%2,%3}, [%4];" \
        : "=r"((r)[0]), "=r"((r)[1]), "=r"((r)[2]), "=r"((r)[3]) : "r"(addr))

#define HMMA16816(d, a, b0, b1) \
    asm volatile("mma.sync.aligned.m16n8k16.row.col.f32.f16.f16.f32 " \
        "{%0,%1,%2,%3},{%4,%5,%6,%7},{%8,%9},{%0,%1,%2,%3};" \
        : "+f"((d)[0]), "+f"((d)[1]), "+f"((d)[2]), "+f"((d)[3]) \
        : "r"((a)[0]), "r"((a)[1]), "r"((a)[2]), "r"((a)[3]), "r"(b0), "r"(b1))

__device__ __forceinline__ float fast_tanh(float v) {
    float t; asm("ex2.approx.f32 %0, %1;" : "=f"(t) : "f"(v * 2.885390081777927f));
    float r; asm("rcp.approx.f32 %0, %1;" : "=f"(r) : "f"(t + 1.0f));
    return fmaf(-2.0f, r, 1.0f);   // tanh(v) = 1 - 2/(e^{2v}+1)
}

// ---------------------------------------------------------------------------
// Kernel 0: W [256,512] fp32 -> fp16 pairs
// ---------------------------------------------------------------------------
__global__ __launch_bounds__(256) void wsplit_kernel(const float* __restrict__ W)
{
    const int i = blockIdx.x * 256 + threadIdx.x;   // pair index
    const float2 v = ((const float2*)W)[i];
    __half2 hp = __floats2half2_rn(v.x, v.y);
    g_wh[i] = *(unsigned int*)&hp;
}

// ---------------------------------------------------------------------------
// Kernel 1: e[t] = sum_a q[a]*tanh( (W x)[t,a] ) via mma.sync fp16.
// CTA tile: M=64 tokens x N=256 (FULL A) — X read once from DRAM.
// 8 warps as 2(m) x 4(n); warp tile 32x64; K chunks of 64.
// ---------------------------------------------------------------------------
#define RSTRIDE 144              // bytes per smem row (64 fp16 + pad)
#define SM_X    0                // 64 rows  * 144 = 9216
#define SM_W    9216             // 256 rows * 144 = 36864
#define SM_Q    46080            // 256 floats
#define SM_TOTAL 47104

__global__ __launch_bounds__(256, 2) void e_mma_kernel(
    const float* __restrict__ x, const float* __restrict__ q)
{
    extern __shared__ __align__(128) char smem[];
    const uint32_t sb = smem_u32(smem);
    const int tid  = threadIdx.x;
    const int lane = tid & 31;
    const int warp = tid >> 5;
    const int warp_m = warp & 1;
    const int warp_n = warp >> 1;
    const size_t m0 = (size_t)blockIdx.x * 64;

    float* sq = (float*)(smem + SM_Q);
    sq[tid] = q[tid];

    float acc[2][8][4];
#pragma unroll
    for (int mt = 0; mt < 2; mt++)
#pragma unroll
        for (int nt = 0; nt < 8; nt++)
#pragma unroll
            for (int j = 0; j < 4; j++) acc[mt][nt][j] = 0.f;

    // per-lane ldmatrix address offsets (bytes)
    const uint32_t a_off = (lane & 15) * RSTRIDE + ((lane >> 4) << 4);
    const uint32_t b_off = ((((lane >> 4) & 1) << 3) + (lane & 7)) * RSTRIDE
                         + (((lane >> 3) & 1) << 4);
    const uint32_t ax = sb + SM_X + warp_m * 32 * RSTRIDE + a_off;
    const uint32_t bw = sb + SM_W + warp_n * 64 * RSTRIDE + b_off;

    const uint4* wh4 = (const uint4*)g_wh;   // [a][64 uint4 per row]

    for (int c = 0; c < 8; c++) {
        const int kk = c * 64;

        // Prefetch X fp32 tile (64 x 64) into regs (overlaps prev compute)
        float4 xv[4];
#pragma unroll
        for (int i = 0; i < 4; i++) {
            const int idx = i * 256 + tid;
            const int row = idx >> 4;
            const int f4  = idx & 15;
            xv[i] = *(const float4*)(x + (m0 + row) * HH + kk + f4 * 4);
        }
        // Prefetch W tile (256 rows x 64 k) fp16 — L2-hot
        uint4 wv[8];
#pragma unroll
        for (int i = 0; i < 8; i++) {
            const int g  = i * 256 + tid;      // uint4 index, 2048 total
            const int row = g >> 3;
            const int cc  = g & 7;
            wv[i] = wh4[(size_t)row * 64 + (kk >> 3) + cc];
        }

        __syncthreads();   // prev chunk's ldmatrix reads complete

        // X -> fp16 into smem
#pragma unroll
        for (int i = 0; i < 4; i++) {
            const int idx = i * 256 + tid;
            const int row = idx >> 4;
            const int f4  = idx & 15;
            const uint32_t bo = row * RSTRIDE + f4 * 8;
            __half2 h01 = __floats2half2_rn(xv[i].x, xv[i].y);
            __half2 h23 = __floats2half2_rn(xv[i].z, xv[i].w);
            unsigned long long hp;
            asm("mov.b64 %0, {%1, %2};" : "=l"(hp)
                : "r"(*(unsigned int*)&h01), "r"(*(unsigned int*)&h23));
            *(unsigned long long*)(smem + SM_X + bo) = hp;
        }
        // W -> smem
#pragma unroll
        for (int i = 0; i < 8; i++) {
            const int g  = i * 256 + tid;
            const int row = g >> 3;
            const int cc  = g & 7;
            *(uint4*)(smem + SM_W + row * RSTRIDE + cc * 16) = wv[i];
        }

        __syncthreads();

        // 4 k-steps
#pragma unroll
        for (int ks = 0; ks < 4; ks++) {
            uint32_t Bv[16];
#pragma unroll
            for (int jp = 0; jp < 4; jp++)
                LDSM_X4(&Bv[jp * 4], bw + jp * 16 * RSTRIDE + ks * 32);
            uint32_t A0[4], A1[4];
            LDSM_X4(A0, ax + ks * 32);
            LDSM_X4(A1, ax + 16 * RSTRIDE + ks * 32);
#pragma unroll
            for (int nt = 0; nt < 8; nt++) {
                const int bi = (nt >> 1) * 4 + (nt & 1) * 2;
                HMMA16816(acc[0][nt], A0, Bv[bi], Bv[bi + 1]);
            }
#pragma unroll
            for (int nt = 0; nt < 8; nt++) {
                const int bi = (nt >> 1) * 4 + (nt & 1) * 2;
                HMMA16816(acc[1][nt], A1, Bv[bi], Bv[bi + 1]);
            }
        }
    }

    // Epilogue: s = sum_cols q[col]*tanh(D) per owned row
    float s[2][2] = {{0.f, 0.f}, {0.f, 0.f}};
#pragma unroll
    for (int mt = 0; mt < 2; mt++)
#pragma unroll
        for (int nt = 0; nt < 8; nt++) {
            const int col = warp_n * 64 + nt * 8 + 2 * (lane & 3);
            const float q0 = sq[col], q1 = sq[col + 1];
            s[mt][0] = fmaf(q0, fast_tanh(acc[mt][nt][0]),
                       fmaf(q1, fast_tanh(acc[mt][nt][1]), s[mt][0]));
            s[mt][1] = fmaf(q0, fast_tanh(acc[mt][nt][2]),
                       fmaf(q1, fast_tanh(acc[mt][nt][3]), s[mt][1]));
        }
#pragma unroll
    for (int mt = 0; mt < 2; mt++)
#pragma unroll
        for (int rh = 0; rh < 2; rh++) {
            float v = s[mt][rh];
            v += __shfl_xor_sync(0xffffffffu, v, 1);
            v += __shfl_xor_sync(0xffffffffu, v, 2);
            s[mt][rh] = v;
        }

    __syncthreads();               // all ldmatrix done; reuse smem
    float* red = (float*)smem;     // [4 warp_n][64 rows]
    if ((lane & 3) == 0) {
#pragma unroll
        for (int mt = 0; mt < 2; mt++)
#pragma unroll
            for (int rh = 0; rh < 2; rh++)
                red[warp_n * 64 + warp_m * 32 + mt * 16 + rh * 8 + (lane >> 2)]
                    = s[mt][rh];
    }
    __syncthreads();
    if (tid < 64)
        g_e[m0 + tid] = (red[tid] + red[64 + tid])
                      + (red[128 + tid] + red[192 + tid]);
}

// ---------------------------------------------------------------------------
// Kernel 2: per-batch  w_t = exp(e_t - max), inclusive prefix P_s, ip = 1/P_s
// ---------------------------------------------------------------------------
__global__ __launch_bounds__(256) void scan_kernel()
{
    __shared__ float se[SS];
    __shared__ float sr[256];
    const int b   = blockIdx.x;
    const int tid = threadIdx.x;
    const int base = b * SS;

    for (int i = tid; i < SS; i += 256) se[i] = g_e[base + i];
    __syncthreads();

    float m = -1e30f;
    for (int i = tid; i < SS; i += 256) m = fmaxf(m, se[i]);
    sr[tid] = m;
    __syncthreads();
    for (int o = 128; o; o >>= 1) {
        if (tid < o) sr[tid] = fmaxf(sr[tid], sr[tid + o]);
        __syncthreads();
    }
    const float M = sr[0];
    __syncthreads();

    const int j0 = tid * 8;
    float wloc[8];
    float run = 0.f;
#pragma unroll
    for (int j = 0; j < 8; j++) {
        wloc[j] = expf(se[j0 + j] - M);
        run += wloc[j];
    }
    sr[tid] = run;
    __syncthreads();
    for (int o = 1; o < 256; o <<= 1) {
        const float v = (tid >= o) ? sr[tid - o] : 0.f;
        __syncthreads();
        sr[tid] += v;
        __syncthreads();
    }
    float acc = sr[tid] - run;
#pragma unroll
    for (int j = 0; j < 8; j++) {
        acc += wloc[j];
        g_w [base + j0 + j] = wloc[j];
        g_ip[base + j0 + j] = 1.0f / acc;
    }
}

// ---------------------------------------------------------------------------
// Kernel 3a: chunk sums T[b,c,h] = sum_{t in chunk} w_t * x[b,t,h]
// ---------------------------------------------------------------------------
__global__ __launch_bounds__(128) void chunk_kernel(const float* __restrict__ x)
{
    __shared__ float sw[CS];
    const int c = blockIdx.x;
    const int b = blockIdx.y;
    const int tbase = b * SS + c * CS;
    if (threadIdx.x < CS) sw[threadIdx.x] = g_w[tbase + threadIdx.x];
    __syncthreads();

    const float4* xp = (const float4*)(x + (size_t)tbase * HH) + threadIdx.x;
    float4 s = make_float4(0.f, 0.f, 0.f, 0.f);
#pragma unroll
    for (int t = 0; t < CS; t++) {
        const float4 v = xp[t * (HH/4)];
        const float w = sw[t];
        s.x = fmaf(w, v.x, s.x);
        s.y = fmaf(w, v.y, s.y);
        s.z = fmaf(w, v.z, s.z);
        s.w = fmaf(w, v.w, s.w);
    }
    ((float4*)(g_chunk + (size_t)(b * NC + c) * HH))[threadIdx.x] = s;
}

// ---------------------------------------------------------------------------
// Kernel 3p: exclusive prefix over chunks
// ---------------------------------------------------------------------------
__global__ __launch_bounds__(128) void chunkpre_kernel()
{
    const int b = blockIdx.x;
    const int h = blockIdx.y * 128 + threadIdx.x;
    float acc = 0.f;
#pragma unroll 4
    for (int c = 0; c < NC; c++) {
        const size_t idx = (size_t)(b * NC + c) * HH + h;
        const float v = g_chunk[idx];
        g_chunkpre[idx] = acc;
        acc += v;
    }
}

// ---------------------------------------------------------------------------
// Kernel 3b: a[b,s,h] = (chunkpre + running sum) * ip[b,s]
// ---------------------------------------------------------------------------
__global__ __launch_bounds__(128) void a_kernel(
    const float* __restrict__ x, float* __restrict__ a_out)
{
    __shared__ float sw[CS];
    __shared__ float sip[CS];
    const int c = blockIdx.x;
    const int b = blockIdx.y;
    const int tbase = b * SS + c * CS;
    if (threadIdx.x < CS) {
        sw [threadIdx.x] = g_w [tbase + threadIdx.x];
        sip[threadIdx.x] = g_ip[tbase + threadIdx.x];
    }
    __syncthreads();

    float4 acc = ((const float4*)(g_chunkpre + (size_t)(b * NC + c) * HH))[threadIdx.x];

    const float4* xp = (const float4*)(x + (size_t)tbase * HH) + threadIdx.x;
    float4* op = (float4*)(a_out + (size_t)tbase * HH) + threadIdx.x;
#pragma unroll
    for (int t = 0; t < CS; t++) {
        const float4 v = xp[t * (HH/4)];
        const float w = sw[t];
        acc.x = fmaf(w, v.x, acc.x);
        acc.y = fmaf(w, v.y, acc.y);
        acc.z = fmaf(w, v.z, acc.z);
        acc.w = fmaf(w, v.w, acc.w);
        const float ip = sip[t];
        __stcs(op + t * (HH/4),
               make_float4(acc.x * ip, acc.y * ip, acc.z * ip, acc.w * ip));
    }
}

// ---------------------------------------------------------------------------
// Kernel 4: d[b,s,t] = (t<=s) ? w[b,t]*ip[b,s] : 0  — 16 rows per CTA,
// w row staged in smem once (kills the per-row 8KB L2 re-read).
// ---------------------------------------------------------------------------
#define DROWS 16
__global__ __launch_bounds__(256) void d_kernel(float* __restrict__ dd)
{
    __shared__ float4 sw4[SS/4];   // 8 KB
    __shared__ float sip[DROWS];
    const int blk = blockIdx.x;            // 2048 blocks
    const int b  = blk >> 7;               // 128 blocks per batch
    const int s0 = (blk & 127) * DROWS;

    const float4* w4 = (const float4*)(g_w + ((size_t)b << 11));
    for (int i = threadIdx.x; i < SS/4; i += 256) sw4[i] = w4[i];
    if (threadIdx.x < DROWS) sip[threadIdx.x] = g_ip[(b << 11) + s0 + threadIdx.x];
    __syncthreads();

#pragma unroll 4
    for (int r = 0; r < DROWS; r++) {
        const int s = s0 + r;
        const float ip = sip[r];
        float4* o4 = (float4*)(dd + ((size_t)(b << 11) + s) * SS);
#pragma unroll
        for (int it = 0; it < 2; it++) {
            const int i = it * 256 + threadIdx.x;
            const int t0 = i * 4;
            float4 out;
            if (t0 + 3 <= s) {
                const float4 wv = sw4[i];
                out.x = wv.x * ip; out.y = wv.y * ip;
                out.z = wv.z * ip; out.w = wv.w * ip;
            } else if (t0 > s) {
                out.x = out.y = out.z = out.w = 0.f;
            } else {
                const float4 wv = sw4[i];
                out.x = (t0     <= s) ? wv.x * ip : 0.f;
                out.y = (t0 + 1 <= s) ? wv.y * ip : 0.f;
                out.z = (t0 + 2 <= s) ? wv.z * ip : 0.f;
                out.w = (t0 + 3 <= s) ? wv.w * ip : 0.f;
            }
            __stcs(o4 + i, out);
        }
    }
}

// ---------------------------------------------------------------------------
extern "C" void kernel_launch(void* const* d_in, const int* in_sizes, int n_in,
                              void* d_out, int out_size)
{
    const float* x = (const float*)d_in[0];   // [B,S,H]
    const float* W = (const float*)d_in[1];   // [A,H]
    const float* q = (const float*)d_in[2];   // [1,A]
    float* a_out = (float*)d_out;             // [B,S,1,H]
    float* dd    = (float*)d_out + A_ELEMS;   // [B,S,1,S]

    cudaFuncSetAttribute(e_mma_kernel,
                         cudaFuncAttributeMaxDynamicSharedMemorySize, SM_TOTAL);

    wsplit_kernel  <<<AA * HH / 512, 256>>>(W);
    e_mma_kernel   <<<BS / 64, 256, SM_TOTAL>>>(x, q);
    scan_kernel    <<<BB, 256>>>();
    chunk_kernel   <<<dim3(NC, BB), 128>>>(x);
    chunkpre_kernel<<<dim3(BB, HH / 128), 128>>>();
    a_kernel       <<<dim3(NC, BB), 128>>>(x, a_out);
    d_kernel       <<<BS / DROWS, 256>>>(dd);
}